// round 2
// baseline (speedup 1.0000x reference)
#include <cuda_runtime.h>
#include <cstdint>

#define NB 8
#define NPTS 4096
#define ND 64
#define NS 1024
#define FEATBASE (NB*NS*3)   // 24576 floats of new_xyz
#define OUTC 320

// ---------------------------------------------------------------------------
// Kernel 1: farthest point sampling. One block per batch, 1024 threads,
// 4 points/thread in registers. Per iteration: min-dist update, warp-shuffle
// argmax, block argmax via atomicMax on packed (dist, ~idx) key using 3
// rotating slots so reset never races reads. Distances via __fmul_rn/__fadd_rn
// (no FMA contraction) to match the reference lowering; ties -> smaller index.
// ---------------------------------------------------------------------------
__global__ __launch_bounds__(1024) void fps_kernel(const float* __restrict__ xyz,
                                                   float* __restrict__ outxyz) {
    __shared__ unsigned long long red[3];
    __shared__ float s_c[3];
    const int b = blockIdx.x, tid = threadIdx.x;
    const float* X = xyz + (size_t)b * NPTS * 3;

    float px[4], py[4], pz[4], dist[4];
#pragma unroll
    for (int j = 0; j < 4; j++) {
        int i = j * 1024 + tid;
        px[j] = X[3 * i];
        py[j] = X[3 * i + 1];
        pz[j] = X[3 * i + 2];
        dist[j] = 1e10f;
    }
    if (tid < 3) red[tid] = 0ULL;
    if (tid == 0) { s_c[0] = X[0]; s_c[1] = X[1]; s_c[2] = X[2]; }  // farthest = 0
    __syncthreads();

    for (int s = 0; s < NS; s++) {
        const float cx = s_c[0], cy = s_c[1], cz = s_c[2];
        if (tid == 0) {
            float* o = outxyz + ((size_t)b * NS + s) * 3;
            o[0] = cx; o[1] = cy; o[2] = cz;
        }
        float bd = -1.0f; int bi = 0;
#pragma unroll
        for (int j = 0; j < 4; j++) {
            float dx = px[j] - cx, dy = py[j] - cy, dz = pz[j] - cz;
            float d = __fadd_rn(__fadd_rn(__fmul_rn(dx, dx), __fmul_rn(dy, dy)),
                                __fmul_rn(dz, dz));
            float dj = fminf(dist[j], d);
            dist[j] = dj;
            if (dj > bd) { bd = dj; bi = j * 1024 + tid; }  // ascending i, strict >
        }
#pragma unroll
        for (int off = 16; off; off >>= 1) {
            float od = __shfl_down_sync(0xffffffffu, bd, off);
            int   oi = __shfl_down_sync(0xffffffffu, bi, off);
            if (od > bd || (od == bd && oi < bi)) { bd = od; bi = oi; }
        }
        const int slot = s % 3;
        if ((tid & 31) == 0) {
            unsigned long long key =
                (((unsigned long long)__float_as_uint(bd)) << 32) |
                (unsigned long long)(0xFFFFFFFFu - (unsigned)bi);
            atomicMax(&red[slot], key);
        }
        if (tid == 0) red[(slot + 1) % 3] = 0ULL;
        __syncthreads();
        unsigned long long v = red[slot];
        int far = (int)(0xFFFFFFFFu - (unsigned)(v & 0xFFFFFFFFull));
        if ((far & 1023) == tid) {
            int j = far >> 10;
            s_c[0] = px[j]; s_c[1] = py[j]; s_c[2] = pz[j];
        }
        __syncthreads();
    }
}

// ---------------------------------------------------------------------------
// Kernel 2: ball query (ordered first-k append) + grouped MLPs + maxpool.
// One block per (s,b). 128 threads.
// ---------------------------------------------------------------------------
struct Params {
    const float* w[9];
    const float* b[9];
};

__device__ __forceinline__ float nfadd(float a, float b) { return __fadd_rn(a, b); }
__device__ __forceinline__ float nfmul(float a, float b) { return __fmul_rn(a, b); }

template <int CH>
__device__ __forceinline__ void gather_rows(const float* __restrict__ X,
                                            const float* __restrict__ F,
                                            const int* __restrict__ gidx,
                                            float cx, float cy, float cz,
                                            float* __restrict__ s_in /* [CH][69] */) {
    const int tid = threadIdx.x;
    for (int e = tid; e < CH * 64; e += 128) {
        int r = e >> 6, c = e & 63;
        s_in[r * 69 + 3 + c] = F[(size_t)gidx[r] * 64 + c];
    }
    for (int e = tid; e < CH * 3; e += 128) {
        int r = e / 3, c = e - r * 3;
        float ctr = (c == 0) ? cx : ((c == 1) ? cy : cz);
        s_in[r * 69 + c] = X[(size_t)gidx[r] * 3 + c] - ctr;
    }
}

// 4 rows x OP output channels per thread; relu; write to strided smem.
template <int CIN, int COUT, int INS, int OUTS, int RG, int OP>
__device__ __forceinline__ void layer(const float* __restrict__ s_a,
                                      float* __restrict__ s_b,
                                      const float* __restrict__ W,
                                      const float* __restrict__ bias) {
    for (int e = threadIdx.x; e < RG * (COUT / OP); e += 128) {
        int rg = e & (RG - 1);
        int o = (e / RG) * OP;
        float acc[OP][4];
#pragma unroll
        for (int j = 0; j < OP; j++) {
            float bv = __ldg(bias + o + j);
            acc[j][0] = bv; acc[j][1] = bv; acc[j][2] = bv; acc[j][3] = bv;
        }
        const float* p = s_a + rg * 4 * INS;
#pragma unroll 4
        for (int c = 0; c < CIN; c++) {
            float v0 = p[c], v1 = p[INS + c], v2 = p[2 * INS + c], v3 = p[3 * INS + c];
#pragma unroll
            for (int j = 0; j < OP; j++) {
                float w = __ldg(W + (o + j) * CIN + c);
                acc[j][0] = fmaf(v0, w, acc[j][0]);
                acc[j][1] = fmaf(v1, w, acc[j][1]);
                acc[j][2] = fmaf(v2, w, acc[j][2]);
                acc[j][3] = fmaf(v3, w, acc[j][3]);
            }
        }
#pragma unroll
        for (int j = 0; j < OP; j++) {
            float* q = s_b + rg * 4 * OUTS + o + j;
            q[0]        = fmaxf(acc[j][0], 0.f);
            q[OUTS]     = fmaxf(acc[j][1], 0.f);
            q[2 * OUTS] = fmaxf(acc[j][2], 0.f);
            q[3 * OUTS] = fmaxf(acc[j][3], 0.f);
        }
    }
}

// Final layer: relu(max over the 4 rows), merged into per-channel atomicMax.
template <int CIN, int COUT, int INS, int RG, int OP>
__device__ __forceinline__ void layer_pool(const float* __restrict__ s_a,
                                           int* __restrict__ omax,
                                           const float* __restrict__ W,
                                           const float* __restrict__ bias) {
    for (int e = threadIdx.x; e < RG * (COUT / OP); e += 128) {
        int rg = e & (RG - 1);
        int o = (e / RG) * OP;
        float acc[OP][4];
#pragma unroll
        for (int j = 0; j < OP; j++) {
            float bv = __ldg(bias + o + j);
            acc[j][0] = bv; acc[j][1] = bv; acc[j][2] = bv; acc[j][3] = bv;
        }
        const float* p = s_a + rg * 4 * INS;
#pragma unroll 4
        for (int c = 0; c < CIN; c++) {
            float v0 = p[c], v1 = p[INS + c], v2 = p[2 * INS + c], v3 = p[3 * INS + c];
#pragma unroll
            for (int j = 0; j < OP; j++) {
                float w = __ldg(W + (o + j) * CIN + c);
                acc[j][0] = fmaf(v0, w, acc[j][0]);
                acc[j][1] = fmaf(v1, w, acc[j][1]);
                acc[j][2] = fmaf(v2, w, acc[j][2]);
                acc[j][3] = fmaf(v3, w, acc[j][3]);
            }
        }
#pragma unroll
        for (int j = 0; j < OP; j++) {
            float m = fmaxf(fmaxf(acc[j][0], acc[j][1]), fmaxf(acc[j][2], acc[j][3]));
            m = fmaxf(m, 0.f);
            atomicMax(&omax[o + j], __float_as_int(m));  // all values >= 0
        }
    }
}

template <int K, int C1, int C2, int C3, int OPA, int OPB, int OPP>
__device__ __forceinline__ void run_scale(const float* X, const float* F,
                                          const int* gidx, float cx, float cy, float cz,
                                          const float* w1, const float* b1,
                                          const float* w2, const float* b2,
                                          const float* w3, const float* b3,
                                          float* s_in, float* s_h1, float* s_h2,
                                          int* s_omax, float* __restrict__ gout) {
    constexpr int CH = (K < 32) ? K : 32;
    constexpr int RG = CH / 4;
    for (int e = threadIdx.x; e < C3; e += 128) s_omax[e] = 0;
    __syncthreads();
    for (int ch = 0; ch < K / CH; ch++) {
        gather_rows<CH>(X, F, gidx + ch * CH, cx, cy, cz, s_in);
        __syncthreads();
        layer<67, C1, 69, C1 + 1, RG, OPA>(s_in, s_h1, w1, b1);
        __syncthreads();
        layer<C1, C2, C1 + 1, C2 + 1, RG, OPB>(s_h1, s_h2, w2, b2);
        __syncthreads();
        layer_pool<C2, C3, C2 + 1, RG, OPP>(s_h2, s_omax, w3, b3);
        __syncthreads();
    }
    for (int e = threadIdx.x; e < C3; e += 128) gout[e] = __int_as_float(s_omax[e]);
    __syncthreads();
}

__global__ __launch_bounds__(128) void group_mlp_kernel(const float* __restrict__ xyz,
                                                        const float* __restrict__ feat,
                                                        const float* __restrict__ newxyz,
                                                        float* __restrict__ out,
                                                        Params P) {
    __shared__ int s_idx[176];           // 16 + 32 + 128
    __shared__ int s_wc[3][4];
    __shared__ int s_cnt[3];
    __shared__ float s_in[32 * 69];
    __shared__ float s_h1[32 * 65];
    __shared__ float s_h2[32 * 97];
    __shared__ int s_omax[128];

    const int s = blockIdx.x, b = blockIdx.y, tid = threadIdx.x;
    const int lane = tid & 31, w = tid >> 5;
    const float* X = xyz + (size_t)b * NPTS * 3;
    const float* F = feat + (size_t)b * NPTS * ND;
    const float* nc = newxyz + ((size_t)b * NS + s) * 3;
    const float cx = __ldg(nc), cy = __ldg(nc + 1), cz = __ldg(nc + 2);
    const float csq = nfadd(nfadd(nfmul(cx, cx), nfmul(cy, cy)), nfmul(cz, cz));

    const float r2_0 = (float)(0.1 * 0.1);
    const float r2_1 = (float)(0.2 * 0.2);
    const float r2_2 = (float)(0.4 * 0.4);

    if (tid < 3) s_cnt[tid] = 0;
    if (tid == 0) { s_idx[0] = 0; s_idx[16] = 0; s_idx[48] = 0; }
    __syncthreads();

    const unsigned lmask = (1u << lane) - 1u;

    for (int base = 0; base < NPTS; base += 128) {
        const int c0 = s_cnt[0], c1 = s_cnt[1], c2 = s_cnt[2];
        const int i = base + tid;
        float x = X[3 * i], y = X[3 * i + 1], z = X[3 * i + 2];
        float xsq = nfadd(nfadd(nfmul(x, x), nfmul(y, y)), nfmul(z, z));
        float dot = nfadd(nfadd(nfmul(x, cx), nfmul(y, cy)), nfmul(z, cz));
        float sqd = nfadd(nfadd(csq, xsq), -nfmul(2.0f, dot));
        bool f0 = !(sqd > r2_0);
        bool f1 = !(sqd > r2_1);
        bool f2 = !(sqd > r2_2);
        unsigned m0 = __ballot_sync(0xffffffffu, f0);
        unsigned m1 = __ballot_sync(0xffffffffu, f1);
        unsigned m2 = __ballot_sync(0xffffffffu, f2);
        if (lane == 0) {
            s_wc[0][w] = __popc(m0);
            s_wc[1][w] = __popc(m1);
            s_wc[2][w] = __popc(m2);
        }
        __syncthreads();
        int b0 = c0, b1v = c1, b2v = c2;
        for (int ww = 0; ww < w; ww++) {
            b0 += s_wc[0][ww]; b1v += s_wc[1][ww]; b2v += s_wc[2][ww];
        }
        int p0 = b0 + __popc(m0 & lmask);
        int p1 = b1v + __popc(m1 & lmask);
        int p2 = b2v + __popc(m2 & lmask);
        if (f0 && p0 < 16)  s_idx[p0] = i;
        if (f1 && p1 < 32)  s_idx[16 + p1] = i;
        if (f2 && p2 < 128) s_idx[48 + p2] = i;
        int t0 = s_wc[0][0] + s_wc[0][1] + s_wc[0][2] + s_wc[0][3];
        int t1 = s_wc[1][0] + s_wc[1][1] + s_wc[1][2] + s_wc[1][3];
        int t2 = s_wc[2][0] + s_wc[2][1] + s_wc[2][2] + s_wc[2][3];
        if (tid == 0) { s_cnt[0] = c0 + t0; s_cnt[1] = c1 + t1; s_cnt[2] = c2 + t2; }
        __syncthreads();
        if (c0 + t0 >= 16 && c1 + t1 >= 32 && c2 + t2 >= 128) break;
    }

    // pad each list with its first (smallest) index
    {
        int k0 = s_cnt[0] < 16 ? s_cnt[0] : 16;
        int k1 = s_cnt[1] < 32 ? s_cnt[1] : 32;
        int k2 = s_cnt[2] < 128 ? s_cnt[2] : 128;
        int f0i = s_idx[0], f1i = s_idx[16], f2i = s_idx[48];
        for (int j = k0 + tid; j < 16; j += 128)  s_idx[j] = f0i;
        for (int j = k1 + tid; j < 32; j += 128)  s_idx[16 + j] = f1i;
        for (int j = k2 + tid; j < 128; j += 128) s_idx[48 + j] = f2i;
        __syncthreads();
    }

    float* gout = out + FEATBASE + ((size_t)b * NS + s) * OUTC;
    run_scale<16, 32, 32, 64, 1, 1, 2>(X, F, s_idx, cx, cy, cz,
                                       P.w[0], P.b[0], P.w[1], P.b[1], P.w[2], P.b[2],
                                       s_in, s_h1, s_h2, s_omax, gout);
    run_scale<32, 64, 64, 128, 2, 2, 2>(X, F, s_idx + 16, cx, cy, cz,
                                        P.w[3], P.b[3], P.w[4], P.b[4], P.w[5], P.b[5],
                                        s_in, s_h1, s_h2, s_omax, gout + 64);
    run_scale<128, 64, 96, 128, 2, 2, 2>(X, F, s_idx + 48, cx, cy, cz,
                                         P.w[6], P.b[6], P.w[7], P.b[7], P.w[8], P.b[8],
                                         s_in, s_h1, s_h2, s_omax, gout + 192);
}

extern "C" void kernel_launch(void* const* d_in, const int* in_sizes, int n_in,
                              void* d_out, int out_size) {
    const float* xyz  = (const float*)d_in[0];
    const float* feat = (const float*)d_in[1];
    float* out = (float*)d_out;

    Params P;
    for (int i = 0; i < 9; i++) {
        P.w[i] = (const float*)d_in[2 + 2 * i];
        P.b[i] = (const float*)d_in[3 + 2 * i];
    }

    // new_xyz written directly into the output buffer's first 24576 floats
    fps_kernel<<<NB, 1024>>>(xyz, out);

    dim3 grid(NS, NB);
    group_mlp_kernel<<<grid, 128>>>(xyz, feat, out, out, P);
}

// round 4
// speedup vs baseline: 1.8416x; 1.8416x over previous
#include <cuda_runtime.h>
#include <cstdint>

#define NB 8
#define NPTS 4096
#define ND 64
#define NS 1024
#define FEATBASE (NB*NS*3)   // 24576 floats of new_xyz
#define OUTC 320
#define GS 8                 // centers per block
#define TPB 256

// ---------------------------------------------------------------------------
// Kernel 1: farthest point sampling (unchanged from passing version).
// ---------------------------------------------------------------------------
__global__ __launch_bounds__(1024) void fps_kernel(const float* __restrict__ xyz,
                                                   float* __restrict__ outxyz) {
    __shared__ unsigned long long red[3];
    __shared__ float s_c[3];
    const int b = blockIdx.x, tid = threadIdx.x;
    const float* X = xyz + (size_t)b * NPTS * 3;

    float px[4], py[4], pz[4], dist[4];
#pragma unroll
    for (int j = 0; j < 4; j++) {
        int i = j * 1024 + tid;
        px[j] = X[3 * i];
        py[j] = X[3 * i + 1];
        pz[j] = X[3 * i + 2];
        dist[j] = 1e10f;
    }
    if (tid < 3) red[tid] = 0ULL;
    if (tid == 0) { s_c[0] = X[0]; s_c[1] = X[1]; s_c[2] = X[2]; }
    __syncthreads();

    for (int s = 0; s < NS; s++) {
        const float cx = s_c[0], cy = s_c[1], cz = s_c[2];
        if (tid == 0) {
            float* o = outxyz + ((size_t)b * NS + s) * 3;
            o[0] = cx; o[1] = cy; o[2] = cz;
        }
        float bd = -1.0f; int bi = 0;
#pragma unroll
        for (int j = 0; j < 4; j++) {
            float dx = px[j] - cx, dy = py[j] - cy, dz = pz[j] - cz;
            float d = __fadd_rn(__fadd_rn(__fmul_rn(dx, dx), __fmul_rn(dy, dy)),
                                __fmul_rn(dz, dz));
            float dj = fminf(dist[j], d);
            dist[j] = dj;
            if (dj > bd) { bd = dj; bi = j * 1024 + tid; }
        }
#pragma unroll
        for (int off = 16; off; off >>= 1) {
            float od = __shfl_down_sync(0xffffffffu, bd, off);
            int   oi = __shfl_down_sync(0xffffffffu, bi, off);
            if (od > bd || (od == bd && oi < bi)) { bd = od; bi = oi; }
        }
        const int slot = s % 3;
        if ((tid & 31) == 0) {
            unsigned long long key =
                (((unsigned long long)__float_as_uint(bd)) << 32) |
                (unsigned long long)(0xFFFFFFFFu - (unsigned)bi);
            atomicMax(&red[slot], key);
        }
        if (tid == 0) red[(slot + 1) % 3] = 0ULL;
        __syncthreads();
        unsigned long long v = red[slot];
        int far = (int)(0xFFFFFFFFu - (unsigned)(v & 0xFFFFFFFFull));
        if ((far & 1023) == tid) {
            int j = far >> 10;
            s_c[0] = px[j]; s_c[1] = py[j]; s_c[2] = pz[j];
        }
        __syncthreads();
    }
}

// ---------------------------------------------------------------------------
// Kernel 2: ball query + grouped MLPs + maxpool. 256 threads, 8 centers/block.
// 128-row tiles, lanes own 4 rows, warps own COUT/8 output channels.
// Weights staged in smem, read warp-uniform via float4. Acts odd-stride LDS.
// ---------------------------------------------------------------------------
struct Params {
    const float* w[9];
    const float* b[9];
};

__device__ __forceinline__ float nfadd(float a, float b) { return __fadd_rn(a, b); }
__device__ __forceinline__ float nfmul(float a, float b) { return __fmul_rn(a, b); }

// smem layout (float words); all offsets multiples of 4 (16B aligned)
#define OFF_IDX   0          // 1408 ints (8 centers x 176)
#define OFF_CTR   1408       // 24 floats
#define OFF_OMAX  1432       // 1024 ints (8 x 128 max)
#define OFF_IN    2456       // 128 x 69
#define OFF_H1    11288      // 128 x 65
#define OFF_H2    19608      // 128 x 97
#define OFF_W1    32024      // up to 64 x 68
#define OFF_W2    36376      // up to 96 x 64
#define OFF_W3    42520      // up to 128 x 96
#define SMEM_WORDS 54808
#define SMEM_BYTES (SMEM_WORDS * 4)

template<int CIN, int WST, int COUT>
__device__ __forceinline__ void load_w(const float* __restrict__ W, float* __restrict__ s_w) {
    for (int e = threadIdx.x; e < COUT * WST; e += TPB) {
        int o = e / WST, c = e - o * WST;
        s_w[e] = (c < CIN) ? __ldg(W + o * CIN + c) : 0.f;
    }
}

template<int K, int LOGK, int LOFF>
__device__ __forceinline__ void gather128(const float* __restrict__ X,
                                          const float* __restrict__ F,
                                          const int* __restrict__ s_idx,
                                          const float* __restrict__ s_ctr,
                                          int cbase, float* __restrict__ s_in) {
    // features via float4 (128 rows x 16 quads)
    for (int e = threadIdx.x; e < 128 * 16; e += TPB) {
        int r = e >> 4, q = e & 15;
        int cb = cbase + (r >> LOGK);
        int gi = s_idx[cb * 176 + LOFF + (r & (K - 1))];
        float4 v = *(const float4*)(F + (size_t)gi * 64 + q * 4);
        float* d = s_in + r * 69 + 3 + q * 4;
        d[0] = v.x; d[1] = v.y; d[2] = v.z; d[3] = v.w;
    }
    // xyz (centered) + zero pad col 67
    for (int e = threadIdx.x; e < 128 * 4; e += TPB) {
        int r = e >> 2, cc = e & 3;
        int cb = cbase + (r >> LOGK);
        if (cc == 3) {
            s_in[r * 69 + 67] = 0.f;
        } else {
            int gi = s_idx[cb * 176 + LOFF + (r & (K - 1))];
            s_in[r * 69 + cc] = X[(size_t)gi * 3 + cc] - s_ctr[cb * 3 + cc];
        }
    }
}

template<int CINP, int WST, int COUT, int INS, int OT>
__device__ __forceinline__ void accum(const float* __restrict__ s_a,
                                      const float* __restrict__ s_w,
                                      const float* __restrict__ gbias,
                                      int lane, int o0, float acc[4][OT]) {
#pragma unroll
    for (int j2 = 0; j2 < OT; j2++) {
        float bv = __ldg(gbias + o0 + j2);
#pragma unroll
        for (int j = 0; j < 4; j++) acc[j][j2] = bv;
    }
    const float* pa = s_a + lane * INS;
    const float* pw = s_w + o0 * WST;
    for (int c = 0; c < CINP; c += 4) {
        float a[4][4];
#pragma unroll
        for (int j = 0; j < 4; j++) {
#pragma unroll
            for (int q = 0; q < 4; q++) a[j][q] = pa[(32 * j) * INS + c + q];
        }
#pragma unroll
        for (int j2 = 0; j2 < OT; j2++) {
            float4 wv = *(const float4*)(pw + j2 * WST + c);
#pragma unroll
            for (int j = 0; j < 4; j++) {
                float t = fmaf(a[j][0], wv.x, acc[j][j2]);
                t = fmaf(a[j][1], wv.y, t);
                t = fmaf(a[j][2], wv.z, t);
                acc[j][j2] = fmaf(a[j][3], wv.w, t);
            }
        }
    }
}

template<int CINP, int WST, int COUT, int INS, int OUTS>
__device__ __forceinline__ void layer_mid(const float* __restrict__ s_a,
                                          float* __restrict__ s_b,
                                          const float* __restrict__ s_w,
                                          const float* __restrict__ gbias) {
    constexpr int OT = COUT / 8;
    const int lane = threadIdx.x & 31;
    const int o0 = (threadIdx.x >> 5) * OT;
    float acc[4][OT];
    accum<CINP, WST, COUT, INS, OT>(s_a, s_w, gbias, lane, o0, acc);
    float* pb = s_b + lane * OUTS + o0;
#pragma unroll
    for (int j2 = 0; j2 < OT; j2++)
#pragma unroll
        for (int j = 0; j < 4; j++)
            pb[(32 * j) * OUTS + j2] = fmaxf(acc[j][j2], 0.f);
}

template<int CINP, int WST, int COUT, int INS, int LOGK>
__device__ __forceinline__ void layer_last(const float* __restrict__ s_a,
                                           int* __restrict__ s_omax,
                                           const float* __restrict__ s_w,
                                           const float* __restrict__ gbias,
                                           int cbase) {
    constexpr int OT = COUT / 8;
    const int lane = threadIdx.x & 31;
    const int o0 = (threadIdx.x >> 5) * OT;
    float acc[4][OT];
    accum<CINP, WST, COUT, INS, OT>(s_a, s_w, gbias, lane, o0, acc);
#pragma unroll
    for (int j2 = 0; j2 < OT; j2++) {
        if (LOGK == 7) {
            // whole tile is one center: warp pre-reduce then 1 atomic/warp
            float m = fmaxf(fmaxf(acc[0][j2], acc[1][j2]), fmaxf(acc[2][j2], acc[3][j2]));
            m = fmaxf(m, 0.f);
#pragma unroll
            for (int off = 16; off; off >>= 1)
                m = fmaxf(m, __shfl_xor_sync(0xffffffffu, m, off));
            if (lane == 0)
                atomicMax(&s_omax[cbase * COUT + o0 + j2], __float_as_int(m));
        } else {
#pragma unroll
            for (int j = 0; j < 4; j++) {
                int cb = cbase + ((lane + 32 * j) >> LOGK);
                atomicMax(&s_omax[cb * COUT + o0 + j2],
                          __float_as_int(fmaxf(acc[j][j2], 0.f)));
            }
        }
    }
}

template<int K, int LOGK, int LOFF, int C1, int C2, int C3>
__device__ __forceinline__ void run_scale(const float* __restrict__ X,
                                          const float* __restrict__ F,
                                          float* __restrict__ sm,
                                          const Params& P, int widx,
                                          float* __restrict__ gout /* +scale offset */) {
    float* s_ctr = sm + OFF_CTR;
    int* s_idx = (int*)(sm + OFF_IDX);
    int* s_omax = (int*)(sm + OFF_OMAX);
    float* s_in = sm + OFF_IN;
    float* s_h1 = sm + OFF_H1;
    float* s_h2 = sm + OFF_H2;
    float* s_w1 = sm + OFF_W1;
    float* s_w2 = sm + OFF_W2;
    float* s_w3 = sm + OFF_W3;

    load_w<67, 68, C1>(P.w[widx], s_w1);
    load_w<C1, C1, C2>(P.w[widx + 1], s_w2);
    load_w<C2, C2, C3>(P.w[widx + 2], s_w3);
    for (int e = threadIdx.x; e < GS * C3; e += TPB) s_omax[e] = 0;
    __syncthreads();

    constexpr int CPP = 128 / K;
    constexpr int NPASS = GS / CPP;
    for (int p = 0; p < NPASS; p++) {
        int cbase = p * CPP;
        gather128<K, LOGK, LOFF>(X, F, s_idx, s_ctr, cbase, s_in);
        __syncthreads();
        layer_mid<68, 68, C1, 69, C1 + 1>(s_in, s_h1, s_w1, P.b[widx]);
        __syncthreads();
        layer_mid<C1, C1, C2, C1 + 1, C2 + 1>(s_h1, s_h2, s_w2, P.b[widx + 1]);
        __syncthreads();
        layer_last<C2, C2, C3, C2 + 1, LOGK>(s_h2, s_omax, s_w3, P.b[widx + 2], cbase);
        __syncthreads();
    }
    for (int e = threadIdx.x; e < GS * C3; e += TPB) {
        int cb = e / C3, o = e - cb * C3;
        gout[(size_t)cb * OUTC + o] = __int_as_float(s_omax[e]);
    }
    __syncthreads();
}

__global__ __launch_bounds__(TPB, 1) void group_mlp_kernel(const float* __restrict__ xyz,
                                                           const float* __restrict__ feat,
                                                           const float* __restrict__ newxyz,
                                                           float* __restrict__ out,
                                                           Params P) {
    extern __shared__ float sm[];
    const int s0 = blockIdx.x * GS, b = blockIdx.y, tid = threadIdx.x;
    const int lane = tid & 31, w = tid >> 5;
    const float* X = xyz + (size_t)b * NPTS * 3;
    const float* F = feat + (size_t)b * NPTS * ND;

    float* s_ctr = sm + OFF_CTR;
    int* s_idx = (int*)(sm + OFF_IDX);

    if (tid < GS * 3) s_ctr[tid] = __ldg(newxyz + ((size_t)b * NS + s0) * 3 + tid);
    __syncthreads();

    // ---- ball query: one warp per center, ordered first-k append ----
    {
        const float cx = s_ctr[w * 3], cy = s_ctr[w * 3 + 1], cz = s_ctr[w * 3 + 2];
        const float csq = nfadd(nfadd(nfmul(cx, cx), nfmul(cy, cy)), nfmul(cz, cz));
        const float r2_0 = (float)(0.1 * 0.1);
        const float r2_1 = (float)(0.2 * 0.2);
        const float r2_2 = (float)(0.4 * 0.4);
        int* idx0 = s_idx + w * 176;
        int* idx1 = idx0 + 16;
        int* idx2 = idx0 + 48;
        int c0 = 0, c1 = 0, c2 = 0;
        const unsigned lmask = (1u << lane) - 1u;
        for (int base = 0; base < NPTS; base += 32) {
            int i = base + lane;
            float x = X[3 * i], y = X[3 * i + 1], z = X[3 * i + 2];
            float xsq = nfadd(nfadd(nfmul(x, x), nfmul(y, y)), nfmul(z, z));
            float dot = nfadd(nfadd(nfmul(x, cx), nfmul(y, cy)), nfmul(z, cz));
            float sqd = nfadd(nfadd(csq, xsq), -nfmul(2.0f, dot));
            bool f0 = !(sqd > r2_0);
            bool f1 = !(sqd > r2_1);
            bool f2 = !(sqd > r2_2);
            unsigned m0 = __ballot_sync(0xffffffffu, f0);
            unsigned m1 = __ballot_sync(0xffffffffu, f1);
            unsigned m2 = __ballot_sync(0xffffffffu, f2);
            int p0 = c0 + __popc(m0 & lmask);
            int p1 = c1 + __popc(m1 & lmask);
            int p2 = c2 + __popc(m2 & lmask);
            if (f0 && p0 < 16)  idx0[p0] = i;
            if (f1 && p1 < 32)  idx1[p1] = i;
            if (f2 && p2 < 128) idx2[p2] = i;
            c0 = min(c0 + __popc(m0), 16);
            c1 = min(c1 + __popc(m1), 32);
            c2 = min(c2 + __popc(m2), 128);
            if (c0 == 16 && c1 == 32 && c2 == 128) break;
        }
        __syncwarp();
        int f0i = idx0[0], f1i = idx1[0], f2i = idx2[0];
        for (int j = c0 + lane; j < 16; j += 32)  idx0[j] = f0i;
        for (int j = c1 + lane; j < 32; j += 32)  idx1[j] = f1i;
        for (int j = c2 + lane; j < 128; j += 32) idx2[j] = f2i;
    }
    __syncthreads();

    float* gout = out + FEATBASE + ((size_t)b * NS + s0) * OUTC;
    run_scale<16, 4, 0, 32, 32, 64>(X, F, sm, P, 0, gout);
    run_scale<32, 5, 16, 64, 64, 128>(X, F, sm, P, 3, gout + 64);
    run_scale<128, 7, 48, 64, 96, 128>(X, F, sm, P, 6, gout + 192);
}

extern "C" void kernel_launch(void* const* d_in, const int* in_sizes, int n_in,
                              void* d_out, int out_size) {
    const float* xyz  = (const float*)d_in[0];
    const float* feat = (const float*)d_in[1];
    float* out = (float*)d_out;

    Params P;
    for (int i = 0; i < 9; i++) {
        P.w[i] = (const float*)d_in[2 + 2 * i];
        P.b[i] = (const float*)d_in[3 + 2 * i];
    }

    cudaFuncSetAttribute(group_mlp_kernel,
                         cudaFuncAttributeMaxDynamicSharedMemorySize, SMEM_BYTES);

    fps_kernel<<<NB, 1024>>>(xyz, out);

    dim3 grid(NS / GS, NB);
    group_mlp_kernel<<<grid, TPB, SMEM_BYTES>>>(xyz, feat, out, out, P);
}

// round 11
// speedup vs baseline: 1.9266x; 1.0461x over previous
#include <cuda_runtime.h>
#include <cstdint>

#define NB 8
#define NPTS 4096
#define ND 64
#define NS 1024
#define FEATBASE (NB*NS*3)   // 24576 floats of new_xyz
#define OUTC 320
#define GS 8                 // centers per block
#define TPB 512
#define NWARP 16

// ---------------------------------------------------------------------------
// f32x2 packed helpers (per-lane .rn -> bit-identical to scalar __fadd_rn/__fmul_rn)
// ---------------------------------------------------------------------------
__device__ __forceinline__ unsigned long long pk2(float lo, float hi) {
    unsigned long long r;
    asm("mov.b64 %0, {%1, %2};" : "=l"(r) : "f"(lo), "f"(hi));
    return r;
}
__device__ __forceinline__ void upk2(unsigned long long v, float& lo, float& hi) {
    asm("mov.b64 {%0, %1}, %2;" : "=f"(lo), "=f"(hi) : "l"(v));
}
__device__ __forceinline__ unsigned long long addx2(unsigned long long a, unsigned long long b) {
    unsigned long long r;
    asm("add.rn.f32x2 %0, %1, %2;" : "=l"(r) : "l"(a), "l"(b));
    return r;
}
__device__ __forceinline__ unsigned long long mulx2(unsigned long long a, unsigned long long b) {
    unsigned long long r;
    asm("mul.rn.f32x2 %0, %1, %2;" : "=l"(r) : "l"(a), "l"(b));
    return r;
}

// ---------------------------------------------------------------------------
// Kernel 1: farthest point sampling. One block per batch, 1024 threads,
// 4 points/thread in registers (packed as 2 x f32x2 per coordinate).
// One __syncthreads per iteration; centroid re-fetched via uniform LDG.
// ---------------------------------------------------------------------------
__global__ __launch_bounds__(1024) void fps_kernel(const float* __restrict__ xyz,
                                                   float* __restrict__ outxyz) {
    __shared__ unsigned long long red[3];
    const int b = blockIdx.x, tid = threadIdx.x;
    const float* X = xyz + (size_t)b * NPTS * 3;

    unsigned long long px2[2], py2[2], pz2[2];
    float dist[4];
#pragma unroll
    for (int jp = 0; jp < 2; jp++) {
        int i0 = (2 * jp) * 1024 + tid;
        int i1 = (2 * jp + 1) * 1024 + tid;
        px2[jp] = pk2(X[3 * i0],     X[3 * i1]);
        py2[jp] = pk2(X[3 * i0 + 1], X[3 * i1 + 1]);
        pz2[jp] = pk2(X[3 * i0 + 2], X[3 * i1 + 2]);
        dist[2 * jp] = 1e10f;
        dist[2 * jp + 1] = 1e10f;
    }
    if (tid < 3) red[tid] = 0ULL;
    __syncthreads();

    int far = 0;
    for (int s = 0; s < NS; s++) {
        const float cx = __ldg(X + 3 * far);
        const float cy = __ldg(X + 3 * far + 1);
        const float cz = __ldg(X + 3 * far + 2);
        if (tid == 0) {
            float* o = outxyz + ((size_t)b * NS + s) * 3;
            o[0] = cx; o[1] = cy; o[2] = cz;
        }
        const unsigned long long ncx = pk2(-cx, -cx);
        const unsigned long long ncy = pk2(-cy, -cy);
        const unsigned long long ncz = pk2(-cz, -cz);

        float bd = -1.0f; int bi = 0;
#pragma unroll
        for (int jp = 0; jp < 2; jp++) {
            unsigned long long dx = addx2(px2[jp], ncx);
            unsigned long long dy = addx2(py2[jp], ncy);
            unsigned long long dz = addx2(pz2[jp], ncz);
            unsigned long long d2 = addx2(addx2(mulx2(dx, dx), mulx2(dy, dy)),
                                          mulx2(dz, dz));
            float d0, d1;
            upk2(d2, d0, d1);
            float da = fminf(dist[2 * jp], d0);
            float db = fminf(dist[2 * jp + 1], d1);
            dist[2 * jp] = da;
            dist[2 * jp + 1] = db;
            if (da > bd) { bd = da; bi = (2 * jp) * 1024 + tid; }
            if (db > bd) { bd = db; bi = (2 * jp + 1) * 1024 + tid; }
        }
#pragma unroll
        for (int off = 16; off; off >>= 1) {
            float od = __shfl_down_sync(0xffffffffu, bd, off);
            int   oi = __shfl_down_sync(0xffffffffu, bi, off);
            if (od > bd || (od == bd && oi < bi)) { bd = od; bi = oi; }
        }
        const int slot = s % 3;
        if ((tid & 31) == 0) {
            unsigned long long key =
                (((unsigned long long)__float_as_uint(bd)) << 32) |
                (unsigned long long)(0xFFFFFFFFu - (unsigned)bi);
            atomicMax(&red[slot], key);
        }
        if (tid == 0) red[(slot + 1) % 3] = 0ULL;
        __syncthreads();
        unsigned long long v = red[slot];
        far = (int)(0xFFFFFFFFu - (unsigned)(v & 0xFFFFFFFFull));
    }
}

// ---------------------------------------------------------------------------
// Kernel 2: ball query + grouped MLPs + maxpool. 512 threads, 8 centers/block.
// 128-row tiles, lanes own 4 rows, warps own COUT/16 output channels.
// Weights staged in smem, read warp-uniform via float4. Acts odd-stride LDS.
// ---------------------------------------------------------------------------
struct Params {
    const float* w[9];
    const float* b[9];
};

__device__ __forceinline__ float nfadd(float a, float b) { return __fadd_rn(a, b); }
__device__ __forceinline__ float nfmul(float a, float b) { return __fmul_rn(a, b); }

// smem layout (float words); all offsets multiples of 4 (16B aligned)
#define OFF_IDX   0          // 1408 ints (8 centers x 176)
#define OFF_CTR   1408       // 24 floats
#define OFF_OMAX  1432       // 1024 ints (8 x 128 max)
#define OFF_IN    2456       // 128 x 69
#define OFF_H1    11288      // 128 x 65
#define OFF_H2    19608      // 128 x 97
#define OFF_W1    32024      // up to 64 x 68
#define OFF_W2    36376      // up to 96 x 64
#define OFF_W3    42520      // up to 128 x 96
#define SMEM_WORDS 54808
#define SMEM_BYTES (SMEM_WORDS * 4)

template<int CIN, int WST, int COUT>
__device__ __forceinline__ void load_w(const float* __restrict__ W, float* __restrict__ s_w) {
    for (int e = threadIdx.x; e < COUT * WST; e += TPB) {
        int o = e / WST, c = e - o * WST;
        s_w[e] = (c < CIN) ? __ldg(W + o * CIN + c) : 0.f;
    }
}

template<int K, int LOGK, int LOFF>
__device__ __forceinline__ void gather128(const float* __restrict__ X,
                                          const float* __restrict__ F,
                                          const int* __restrict__ s_idx,
                                          const float* __restrict__ s_ctr,
                                          int cbase, float* __restrict__ s_in) {
    // features via float4 (128 rows x 16 quads)
    for (int e = threadIdx.x; e < 128 * 16; e += TPB) {
        int r = e >> 4, q = e & 15;
        int cb = cbase + (r >> LOGK);
        int gi = s_idx[cb * 176 + LOFF + (r & (K - 1))];
        float4 v = *(const float4*)(F + (size_t)gi * 64 + q * 4);
        float* d = s_in + r * 69 + 3 + q * 4;
        d[0] = v.x; d[1] = v.y; d[2] = v.z; d[3] = v.w;
    }
    // xyz (centered) + zero pad col 67
    for (int e = threadIdx.x; e < 128 * 4; e += TPB) {
        int r = e >> 2, cc = e & 3;
        int cb = cbase + (r >> LOGK);
        if (cc == 3) {
            s_in[r * 69 + 67] = 0.f;
        } else {
            int gi = s_idx[cb * 176 + LOFF + (r & (K - 1))];
            s_in[r * 69 + cc] = X[(size_t)gi * 3 + cc] - s_ctr[cb * 3 + cc];
        }
    }
}

template<int CINP, int WST, int COUT, int INS, int OT>
__device__ __forceinline__ void accum(const float* __restrict__ s_a,
                                      const float* __restrict__ s_w,
                                      const float* __restrict__ gbias,
                                      int lane, int o0, float acc[4][OT]) {
#pragma unroll
    for (int j2 = 0; j2 < OT; j2++) {
        float bv = __ldg(gbias + o0 + j2);
#pragma unroll
        for (int j = 0; j < 4; j++) acc[j][j2] = bv;
    }
    const float* pa = s_a + lane * INS;
    const float* pw = s_w + o0 * WST;
    for (int c = 0; c < CINP; c += 4) {
        float a[4][4];
#pragma unroll
        for (int j = 0; j < 4; j++) {
#pragma unroll
            for (int q = 0; q < 4; q++) a[j][q] = pa[(32 * j) * INS + c + q];
        }
#pragma unroll
        for (int j2 = 0; j2 < OT; j2++) {
            float4 wv = *(const float4*)(pw + j2 * WST + c);
#pragma unroll
            for (int j = 0; j < 4; j++) {
                float t = fmaf(a[j][0], wv.x, acc[j][j2]);
                t = fmaf(a[j][1], wv.y, t);
                t = fmaf(a[j][2], wv.z, t);
                acc[j][j2] = fmaf(a[j][3], wv.w, t);
            }
        }
    }
}

template<int CINP, int WST, int COUT, int INS, int OUTS>
__device__ __forceinline__ void layer_mid(const float* __restrict__ s_a,
                                          float* __restrict__ s_b,
                                          const float* __restrict__ s_w,
                                          const float* __restrict__ gbias) {
    constexpr int OT = COUT / NWARP;
    const int lane = threadIdx.x & 31;
    const int o0 = (threadIdx.x >> 5) * OT;
    float acc[4][OT];
    accum<CINP, WST, COUT, INS, OT>(s_a, s_w, gbias, lane, o0, acc);
    float* pb = s_b + lane * OUTS + o0;
#pragma unroll
    for (int j2 = 0; j2 < OT; j2++)
#pragma unroll
        for (int j = 0; j < 4; j++)
            pb[(32 * j) * OUTS + j2] = fmaxf(acc[j][j2], 0.f);
}

template<int CINP, int WST, int COUT, int INS, int LOGK>
__device__ __forceinline__ void layer_last(const float* __restrict__ s_a,
                                           int* __restrict__ s_omax,
                                           const float* __restrict__ s_w,
                                           const float* __restrict__ gbias,
                                           int cbase) {
    constexpr int OT = COUT / NWARP;
    const int lane = threadIdx.x & 31;
    const int o0 = (threadIdx.x >> 5) * OT;
    float acc[4][OT];
    accum<CINP, WST, COUT, INS, OT>(s_a, s_w, gbias, lane, o0, acc);
#pragma unroll
    for (int j2 = 0; j2 < OT; j2++) {
        if (LOGK == 7) {
            // whole tile is one center: warp pre-reduce then 1 atomic/warp
            float m = fmaxf(fmaxf(acc[0][j2], acc[1][j2]), fmaxf(acc[2][j2], acc[3][j2]));
            m = fmaxf(m, 0.f);
#pragma unroll
            for (int off = 16; off; off >>= 1)
                m = fmaxf(m, __shfl_xor_sync(0xffffffffu, m, off));
            if (lane == 0)
                atomicMax(&s_omax[cbase * COUT + o0 + j2], __float_as_int(m));
        } else {
#pragma unroll
            for (int j = 0; j < 4; j++) {
                int cb = cbase + ((lane + 32 * j) >> LOGK);
                atomicMax(&s_omax[cb * COUT + o0 + j2],
                          __float_as_int(fmaxf(acc[j][j2], 0.f)));
            }
        }
    }
}

template<int K, int LOGK, int LOFF, int C1, int C2, int C3>
__device__ __forceinline__ void run_scale(const float* __restrict__ X,
                                          const float* __restrict__ F,
                                          float* __restrict__ sm,
                                          const Params& P, int widx,
                                          float* __restrict__ gout /* +scale offset */) {
    float* s_ctr = sm + OFF_CTR;
    int* s_idx = (int*)(sm + OFF_IDX);
    int* s_omax = (int*)(sm + OFF_OMAX);
    float* s_in = sm + OFF_IN;
    float* s_h1 = sm + OFF_H1;
    float* s_h2 = sm + OFF_H2;
    float* s_w1 = sm + OFF_W1;
    float* s_w2 = sm + OFF_W2;
    float* s_w3 = sm + OFF_W3;

    load_w<67, 68, C1>(P.w[widx], s_w1);
    load_w<C1, C1, C2>(P.w[widx + 1], s_w2);
    load_w<C2, C2, C3>(P.w[widx + 2], s_w3);
    for (int e = threadIdx.x; e < GS * C3; e += TPB) s_omax[e] = 0;
    __syncthreads();

    constexpr int CPP = 128 / K;
    constexpr int NPASS = GS / CPP;
    for (int p = 0; p < NPASS; p++) {
        int cbase = p * CPP;
        gather128<K, LOGK, LOFF>(X, F, s_idx, s_ctr, cbase, s_in);
        __syncthreads();
        layer_mid<68, 68, C1, 69, C1 + 1>(s_in, s_h1, s_w1, P.b[widx]);
        __syncthreads();
        layer_mid<C1, C1, C2, C1 + 1, C2 + 1>(s_h1, s_h2, s_w2, P.b[widx + 1]);
        __syncthreads();
        layer_last<C2, C2, C3, C2 + 1, LOGK>(s_h2, s_omax, s_w3, P.b[widx + 2], cbase);
        __syncthreads();
    }
    for (int e = threadIdx.x; e < GS * C3; e += TPB) {
        int cb = e / C3, o = e - cb * C3;
        gout[(size_t)cb * OUTC + o] = __int_as_float(s_omax[e]);
    }
    __syncthreads();
}

__global__ __launch_bounds__(TPB, 1) void group_mlp_kernel(const float* __restrict__ xyz,
                                                           const float* __restrict__ feat,
                                                           const float* __restrict__ newxyz,
                                                           float* __restrict__ out,
                                                           Params P) {
    extern __shared__ float sm[];
    const int s0 = blockIdx.x * GS, b = blockIdx.y, tid = threadIdx.x;
    const int lane = tid & 31, w = tid >> 5;
    const float* X = xyz + (size_t)b * NPTS * 3;
    const float* F = feat + (size_t)b * NPTS * ND;

    float* s_ctr = sm + OFF_CTR;
    int* s_idx = (int*)(sm + OFF_IDX);

    if (tid < GS * 3) s_ctr[tid] = __ldg(newxyz + ((size_t)b * NS + s0) * 3 + tid);
    __syncthreads();

    // ---- ball query: one warp per center (warps 0..7), ordered first-k append ----
    if (w < GS) {
        const float cx = s_ctr[w * 3], cy = s_ctr[w * 3 + 1], cz = s_ctr[w * 3 + 2];
        const float csq = nfadd(nfadd(nfmul(cx, cx), nfmul(cy, cy)), nfmul(cz, cz));
        const float r2_0 = (float)(0.1 * 0.1);
        const float r2_1 = (float)(0.2 * 0.2);
        const float r2_2 = (float)(0.4 * 0.4);
        int* idx0 = s_idx + w * 176;
        int* idx1 = idx0 + 16;
        int* idx2 = idx0 + 48;
        int c0 = 0, c1 = 0, c2 = 0;
        const unsigned lmask = (1u << lane) - 1u;
        for (int base = 0; base < NPTS; base += 32) {
            int i = base + lane;
            float x = X[3 * i], y = X[3 * i + 1], z = X[3 * i + 2];
            float xsq = nfadd(nfadd(nfmul(x, x), nfmul(y, y)), nfmul(z, z));
            float dot = nfadd(nfadd(nfmul(x, cx), nfmul(y, cy)), nfmul(z, cz));
            float sqd = nfadd(nfadd(csq, xsq), -nfmul(2.0f, dot));
            bool f0 = !(sqd > r2_0);
            bool f1 = !(sqd > r2_1);
            bool f2 = !(sqd > r2_2);
            unsigned m0 = __ballot_sync(0xffffffffu, f0);
            unsigned m1 = __ballot_sync(0xffffffffu, f1);
            unsigned m2 = __ballot_sync(0xffffffffu, f2);
            int p0 = c0 + __popc(m0 & lmask);
            int p1 = c1 + __popc(m1 & lmask);
            int p2 = c2 + __popc(m2 & lmask);
            if (f0 && p0 < 16)  idx0[p0] = i;
            if (f1 && p1 < 32)  idx1[p1] = i;
            if (f2 && p2 < 128) idx2[p2] = i;
            c0 = min(c0 + __popc(m0), 16);
            c1 = min(c1 + __popc(m1), 32);
            c2 = min(c2 + __popc(m2), 128);
            if (c0 == 16 && c1 == 32 && c2 == 128) break;
        }
        __syncwarp();
        int f0i = idx0[0], f1i = idx1[0], f2i = idx2[0];
        for (int j = c0 + lane; j < 16; j += 32)  idx0[j] = f0i;
        for (int j = c1 + lane; j < 32; j += 32)  idx1[j] = f1i;
        for (int j = c2 + lane; j < 128; j += 32) idx2[j] = f2i;
    }
    __syncthreads();

    float* gout = out + FEATBASE + ((size_t)b * NS + s0) * OUTC;
    run_scale<16, 4, 0, 32, 32, 64>(X, F, sm, P, 0, gout);
    run_scale<32, 5, 16, 64, 64, 128>(X, F, sm, P, 3, gout + 64);
    run_scale<128, 7, 48, 64, 96, 128>(X, F, sm, P, 6, gout + 192);
}

extern "C" void kernel_launch(void* const* d_in, const int* in_sizes, int n_in,
                              void* d_out, int out_size) {
    const float* xyz  = (const float*)d_in[0];
    const float* feat = (const float*)d_in[1];
    float* out = (float*)d_out;

    Params P;
    for (int i = 0; i < 9; i++) {
        P.w[i] = (const float*)d_in[2 + 2 * i];
        P.b[i] = (const float*)d_in[3 + 2 * i];
    }

    cudaFuncSetAttribute(group_mlp_kernel,
                         cudaFuncAttributeMaxDynamicSharedMemorySize, SMEM_BYTES);

    fps_kernel<<<NB, 1024>>>(xyz, out);

    dim3 grid(NS / GS, NB);
    group_mlp_kernel<<<grid, TPB, SMEM_BYTES>>>(xyz, feat, out, out, P);
}